// round 9
// baseline (speedup 1.0000x reference)
#include <cuda_runtime.h>
#include <cuda_bf16.h>
#include <cstdint>

// Problem constants (fixed shapes for TopKSAE_128849019036)
#define N_TOK   4096
#define D_MODEL 2048
#define D_SAE   32768
#define KTOP    64

// Scratch for top-k results (sanctioned __device__ globals, no allocation)
__device__ float g_vals[N_TOK * KTOP];
__device__ int   g_idx [N_TOK * KTOP];

// ============================================================================
// Kernel 1: encode GEMM  pre = x @ W_enc + b_enc, NEAR-EXACT fp32.
// Top-k selection is hypersensitive: one near-tie index flip vs the reference
// costs rel_err ~2.5e-3 on x_hat (threshold 1e-3). So pre must be as close to
// the infinitely-precise result as possible: accumulate 64-term chunks in
// plain fp32 FFMA (partial sums small -> error ~5e-8), then fold chunks with
// Neumaier compensated summation (result within ~1 ulp of exact, independent
// of ordering). All compensation arithmetic uses __f*_rn intrinsics so the
// compiler cannot contract or reassociate it.
//
// Tile: BM=128, BN=64, BK=16, 256 threads, 8x4 outputs/thread.
// Register state per thread: acc[32] + sum[32] + comp[32] ~ 120 regs -> 2 CTA/SM.
// ============================================================================
#define BM 128
#define BN 64
#define BK 16
#define KCHUNK 64   // 4 BK-tiles per compensated fold

__device__ __forceinline__ void neumaier_add(float& s, float& c, float a) {
    float t = __fadd_rn(s, a);
    if (fabsf(s) >= fabsf(a))
        c = __fadd_rn(c, __fadd_rn(__fsub_rn(s, t), a));
    else
        c = __fadd_rn(c, __fadd_rn(__fsub_rn(a, t), s));
    s = t;
}

__global__ __launch_bounds__(256, 2)
void encode_gemm(const float* __restrict__ A,   // x [N_TOK, D_MODEL]
                 const float* __restrict__ B,   // W_enc [D_MODEL, D_SAE]
                 const float* __restrict__ bias,
                 float* __restrict__ C)         // pre [N_TOK, D_SAE]
{
    __shared__ float As[BK][BM];   // transposed A tile
    __shared__ float Bs[BK][BN];

    const int tid  = threadIdx.x;
    const int trow = tid >> 4;           // 0..15 -> 8 rows each
    const int tcol = tid & 15;           // 0..15 -> 4 cols each

    // A tile: 128 rows x 16 k = 2048 floats -> 8 per thread (2 float4)
    const int aRow = tid >> 1;           // 0..127
    const int aCol = (tid & 1) << 3;     // 0 or 8
    // B tile: 16 rows x 64 cols = 1024 floats -> 1 float4 per thread
    const int bRow = tid >> 4;           // 0..15
    const int bCol = (tid & 15) << 2;    // 0..60

    const float* Ab = A + (size_t)blockIdx.y * BM * D_MODEL;
    const float* Bb = B + (size_t)blockIdx.x * BN;

    float sum[8][4], comp[8][4], acc[8][4];
#pragma unroll
    for (int i = 0; i < 8; i++)
#pragma unroll
        for (int j = 0; j < 4; j++) {
            sum[i][j] = 0.f; comp[i][j] = 0.f; acc[i][j] = 0.f;
        }

    for (int kc = 0; kc < D_MODEL; kc += KCHUNK) {
#pragma unroll
        for (int t = 0; t < KCHUNK / BK; t++) {
            const int k0 = kc + t * BK;
            float4 a0 = *(const float4*)(Ab + (size_t)aRow * D_MODEL + k0 + aCol);
            float4 a1 = *(const float4*)(Ab + (size_t)aRow * D_MODEL + k0 + aCol + 4);
            float4 bv = *(const float4*)(Bb + (size_t)(k0 + bRow) * D_SAE + bCol);
            __syncthreads();
            As[aCol + 0][aRow] = a0.x;
            As[aCol + 1][aRow] = a0.y;
            As[aCol + 2][aRow] = a0.z;
            As[aCol + 3][aRow] = a0.w;
            As[aCol + 4][aRow] = a1.x;
            As[aCol + 5][aRow] = a1.y;
            As[aCol + 6][aRow] = a1.z;
            As[aCol + 7][aRow] = a1.w;
            *(float4*)(&Bs[bRow][bCol]) = bv;
            __syncthreads();

#pragma unroll
            for (int k = 0; k < BK; k++) {
                float4 ra0 = *(const float4*)(&As[k][trow * 8]);
                float4 ra1 = *(const float4*)(&As[k][trow * 8 + 4]);
                float4 rbv = *(const float4*)(&Bs[k][tcol * 4]);
                float ra[8] = {ra0.x, ra0.y, ra0.z, ra0.w,
                               ra1.x, ra1.y, ra1.z, ra1.w};
                float rb[4] = {rbv.x, rbv.y, rbv.z, rbv.w};
#pragma unroll
                for (int i = 0; i < 8; i++)
#pragma unroll
                    for (int j = 0; j < 4; j++)
                        acc[i][j] = fmaf(ra[i], rb[j], acc[i][j]);
            }
        }
        // fold this 64-term chunk into the compensated accumulator
#pragma unroll
        for (int i = 0; i < 8; i++)
#pragma unroll
            for (int j = 0; j < 4; j++) {
                neumaier_add(sum[i][j], comp[i][j], acc[i][j]);
                acc[i][j] = 0.f;
            }
    }

    const int cbase = blockIdx.x * BN + tcol * 4;
    float bl[4];
#pragma unroll
    for (int j = 0; j < 4; j++) bl[j] = bias[cbase + j];

#pragma unroll
    for (int i = 0; i < 8; i++) {
        size_t row = (size_t)blockIdx.y * BM + trow * 8 + i;
        float* Cr = C + row * D_SAE + cbase;
        float4 v;
        v.x = __fadd_rn(__fadd_rn(sum[i][0], comp[i][0]), bl[0]);
        v.y = __fadd_rn(__fadd_rn(sum[i][1], comp[i][1]), bl[1]);
        v.z = __fadd_rn(__fadd_rn(sum[i][2], comp[i][2]), bl[2]);
        v.w = __fadd_rn(__fadd_rn(sum[i][3], comp[i][3]), bl[3]);
        *(float4*)Cr = v;
    }
}

// ============================================================================
// Kernel 2: per-token top-64 of relu(pre) via exact 4-pass radix select on
// fp32 bit patterns (nonneg floats are uint-order monotone). Deterministic,
// lowest-index-first among equal values at the threshold (matches
// jax.lax.top_k stability). Writes compact (val, idx) to scratch and scatters
// into z (z pre-zeroed by memset). One block per token; row staged in SMEM.
// ============================================================================
__global__ void topk_kernel(const float* __restrict__ pre,
                            float* __restrict__ z)
{
    extern __shared__ unsigned sdata[];   // D_SAE uints = 128 KB
    __shared__ int hist[256];
    __shared__ int s_scan[256];
    __shared__ unsigned s_prefix;
    __shared__ int s_need;

    const int tid = threadIdx.x;          // blockDim.x == 256
    const int n   = blockIdx.x;
    const float* row = pre + (size_t)n * D_SAE;

    for (int i = tid; i < D_SAE; i += 256) {
        float v = row[i];
        sdata[i] = (v > 0.f) ? __float_as_uint(v) : 0u;
    }
    if (tid < KTOP) {
        g_vals[n * KTOP + tid] = 0.f;
        g_idx [n * KTOP + tid] = 0;
    }
    __syncthreads();

    unsigned prefix = 0;
    int need = KTOP;
    for (int shift = 24; shift >= 0; shift -= 8) {
        hist[tid] = 0;
        __syncthreads();
        for (int i = tid; i < D_SAE; i += 256) {
            unsigned x = sdata[i];
            if (x == 0u) continue;
            bool match = (shift == 24) ||
                         ((x >> (shift + 8)) == (prefix >> (shift + 8)));
            if (match) atomicAdd(&hist[(x >> shift) & 255], 1);
        }
        __syncthreads();
        if (tid == 0) {
            int total = 0;
            for (int i = 0; i < 256; i++) total += hist[i];
            int nd = need;
            if (total < nd) nd = total;
            if (nd > 0) {
                int cum = 0, b = 0;
                for (int i = 255; i >= 0; i--) {
                    if (cum + hist[i] >= nd) { b = i; break; }
                    cum += hist[i];
                }
                s_prefix = prefix | ((unsigned)b << shift);
                s_need   = nd - cum;
            } else {
                s_prefix = 0xFFFFFFFFu;
                s_need   = 0;
            }
        }
        __syncthreads();
        prefix = s_prefix;
        need   = s_need;
    }
    const unsigned T = prefix;
    const int needEq = need;

    const int start = tid * (D_SAE / 256);
    int cgt = 0, ceq = 0;
    for (int j = 0; j < D_SAE / 256; j++) {
        unsigned x = sdata[start + j];
        cgt += (x > T);
        ceq += (x == T);
    }

    s_scan[tid] = cgt;
    __syncthreads();
    for (int off = 1; off < 256; off <<= 1) {
        int v = (tid >= off) ? s_scan[tid - off] : 0;
        __syncthreads();
        s_scan[tid] += v;
        __syncthreads();
    }
    const int gtEx    = s_scan[tid] - cgt;
    const int totalGt = s_scan[255];
    __syncthreads();

    s_scan[tid] = ceq;
    __syncthreads();
    for (int off = 1; off < 256; off <<= 1) {
        int v = (tid >= off) ? s_scan[tid - off] : 0;
        __syncthreads();
        s_scan[tid] += v;
        __syncthreads();
    }
    const int eqEx = s_scan[tid] - ceq;

    int g = gtEx, e = eqEx;
    for (int j = 0; j < D_SAE / 256; j++) {
        unsigned x = sdata[start + j];
        int slot = -1;
        if (x > T) {
            slot = g++;
        } else if (x == T) {
            int r = e++;
            if (r < needEq) slot = totalGt + r;
        }
        if (slot >= 0) {
            int fi = start + j;
            float v = __uint_as_float(x);
            g_vals[n * KTOP + slot] = v;
            g_idx [n * KTOP + slot] = fi;
            z[(size_t)n * D_SAE + fi] = v;
        }
    }
}

// ============================================================================
// Kernel 3: sparse decode  x_hat[n] = sum_k v_k * W_dec[idx_k, :] + b_dec
// ============================================================================
__global__ __launch_bounds__(256)
void decode_kernel(const float* __restrict__ Wdec,
                   const float* __restrict__ bdec,
                   float* __restrict__ xhat)
{
    __shared__ float sv[KTOP];
    __shared__ int   si[KTOP];
    const int n = blockIdx.x, tid = threadIdx.x;
    if (tid < KTOP) {
        sv[tid] = g_vals[n * KTOP + tid];
        si[tid] = g_idx [n * KTOP + tid];
    }
    __syncthreads();

    float acc[8];
#pragma unroll
    for (int j = 0; j < 8; j++) acc[j] = bdec[tid + j * 256];

    for (int k = 0; k < KTOP; k++) {
        float v = sv[k];
        const float* wr = Wdec + (size_t)si[k] * D_MODEL;
#pragma unroll
        for (int j = 0; j < 8; j++)
            acc[j] = fmaf(v, wr[tid + j * 256], acc[j]);
    }

    float* orow = xhat + (size_t)n * D_MODEL;
#pragma unroll
    for (int j = 0; j < 8; j++) orow[tid + j * 256] = acc[j];
}

// ============================================================================
// Launch: out = [x_hat | z | pre] (reference return order), all fp32.
// Graph-capturable: kernels + one async memset, no sync, no allocation.
// ============================================================================
extern "C" void kernel_launch(void* const* d_in, const int* in_sizes, int n_in,
                              void* d_out, int out_size)
{
    (void)in_sizes; (void)n_in; (void)out_size;
    const float* x     = (const float*)d_in[0];
    const float* W_enc = (const float*)d_in[1];
    const float* b_enc = (const float*)d_in[2];
    const float* W_dec = (const float*)d_in[3];
    const float* b_dec = (const float*)d_in[4];

    float* out  = (float*)d_out;
    float* xhat = out;
    float* z    = out + (size_t)N_TOK * D_MODEL;
    float* pre  = z   + (size_t)N_TOK * D_SAE;

    cudaMemsetAsync(z, 0, (size_t)N_TOK * D_SAE * sizeof(float), 0);

    dim3 gemm_grid(D_SAE / BN, N_TOK / BM);
    encode_gemm<<<gemm_grid, 256>>>(x, W_enc, b_enc, pre);

    cudaFuncSetAttribute(topk_kernel,
                         cudaFuncAttributeMaxDynamicSharedMemorySize,
                         D_SAE * (int)sizeof(unsigned));
    topk_kernel<<<N_TOK, 256, D_SAE * sizeof(unsigned)>>>(pre, z);

    decode_kernel<<<N_TOK, 256>>>(W_dec, b_dec, xhat);
}

// round 10
// speedup vs baseline: 1.0291x; 1.0291x over previous
#include <cuda_runtime.h>
#include <cuda_bf16.h>
#include <cstdint>

// Problem constants (fixed shapes for TopKSAE_128849019036)
#define N_TOK   4096
#define D_MODEL 2048
#define D_SAE   32768
#define KTOP    64

// Scratch for top-k results (sanctioned __device__ globals, no allocation)
__device__ float g_vals[N_TOK * KTOP];
__device__ int   g_idx [N_TOK * KTOP];

// ============================================================================
// Kernel 1: encode GEMM  pre = x @ W_enc + b_enc, NEAR-EXACT fp32.
//
// Numerics are BITWISE IDENTICAL to the R8 passing kernel (rel_err 4.25e-7):
// per output, sequential-k FFMA chain in 64-term chunks, Neumaier fold per
// chunk, (sum+comp)+bias finish, all via __f*_rn intrinsics. Only the
// tiling/thread mapping changed.
//
// R8 bottleneck (ncu): L1/shared 74.9% busy vs fma 54.9% — the 8x4 thread
// tile needed 1.5 B of LDS per FMA (> 128 B/cyc crossbar at full FMA rate).
// R9 tile: BM=128, BN=128, BK=16, 256 threads, 8x8 per thread
//   -> 1.0 B/FMA (crossbar ~50% at full FMA rate), FMA becomes the limiter.
// 192 accumulator regs -> 1 CTA/SM; double-buffered SMEM (32 KB) with
// gmem->reg prefetch hides load latency, one __syncthreads per BK tile.
// ============================================================================
#define BM 128
#define BN 128
#define BK 16
#define KCHUNK 64   // 4 BK-tiles per compensated fold (DO NOT CHANGE: numerics)

__device__ __forceinline__ void neumaier_add(float& s, float& c, float a) {
    float t = __fadd_rn(s, a);
    if (fabsf(s) >= fabsf(a))
        c = __fadd_rn(c, __fadd_rn(__fsub_rn(s, t), a));
    else
        c = __fadd_rn(c, __fadd_rn(__fsub_rn(a, t), s));
    s = t;
}

__global__ __launch_bounds__(256, 1)
void encode_gemm(const float* __restrict__ A,   // x [N_TOK, D_MODEL]
                 const float* __restrict__ B,   // W_enc [D_MODEL, D_SAE]
                 const float* __restrict__ bias,
                 float* __restrict__ C)         // pre [N_TOK, D_SAE]
{
    __shared__ float As[2][BK][BM];   // transposed A tile, double buffered
    __shared__ float Bs[2][BK][BN];

    const int tid  = threadIdx.x;
    const int trow = tid >> 4;           // 0..15 -> 8 output rows each
    const int tcol = tid & 15;           // 0..15 -> 8 output cols each

    // A tile: 128 rows x 16 k = 2048 floats -> 8/thread (2 float4)
    const int aRow = tid >> 1;           // 0..127
    const int aCol = (tid & 1) << 3;     // 0 or 8
    // B tile: 16 k-rows x 128 cols = 2048 floats -> 8/thread (2 float4)
    const int bRow = tid >> 4;           // 0..15
    const int bCol = (tid & 15) << 3;    // 0..120

    const float* Ab = A + (size_t)blockIdx.y * BM * D_MODEL;
    const float* Bb = B + (size_t)blockIdx.x * BN;

    float sum[8][8], comp[8][8], acc[8][8];
#pragma unroll
    for (int i = 0; i < 8; i++)
#pragma unroll
        for (int j = 0; j < 8; j++) {
            sum[i][j] = 0.f; comp[i][j] = 0.f; acc[i][j] = 0.f;
        }

    const int NT = D_MODEL / BK;   // 128 k-tiles

    // ---- preload tile 0 into buffer 0 ----
    {
        float4 a0 = *(const float4*)(Ab + (size_t)aRow * D_MODEL + aCol);
        float4 a1 = *(const float4*)(Ab + (size_t)aRow * D_MODEL + aCol + 4);
        float4 b0 = *(const float4*)(Bb + (size_t)bRow * D_SAE + bCol);
        float4 b1 = *(const float4*)(Bb + (size_t)bRow * D_SAE + bCol + 4);
        As[0][aCol + 0][aRow] = a0.x;  As[0][aCol + 1][aRow] = a0.y;
        As[0][aCol + 2][aRow] = a0.z;  As[0][aCol + 3][aRow] = a0.w;
        As[0][aCol + 4][aRow] = a1.x;  As[0][aCol + 5][aRow] = a1.y;
        As[0][aCol + 6][aRow] = a1.z;  As[0][aCol + 7][aRow] = a1.w;
        *(float4*)(&Bs[0][bRow][bCol])     = b0;
        *(float4*)(&Bs[0][bRow][bCol + 4]) = b1;
    }
    __syncthreads();

    for (int t = 0; t < NT; t++) {
        const int buf = t & 1;

        // prefetch next tile gmem -> regs (overlaps with compute below)
        float4 a0, a1, b0, b1;
        if (t + 1 < NT) {
            const int k0 = (t + 1) * BK;
            a0 = *(const float4*)(Ab + (size_t)aRow * D_MODEL + k0 + aCol);
            a1 = *(const float4*)(Ab + (size_t)aRow * D_MODEL + k0 + aCol + 4);
            b0 = *(const float4*)(Bb + (size_t)(k0 + bRow) * D_SAE + bCol);
            b1 = *(const float4*)(Bb + (size_t)(k0 + bRow) * D_SAE + bCol + 4);
        }

        // compute on current buffer: sequential k (numerics-order preserved)
#pragma unroll
        for (int k = 0; k < BK; k++) {
            float4 ra0 = *(const float4*)(&As[buf][k][trow * 8]);
            float4 ra1 = *(const float4*)(&As[buf][k][trow * 8 + 4]);
            float4 rb0 = *(const float4*)(&Bs[buf][k][tcol * 8]);
            float4 rb1 = *(const float4*)(&Bs[buf][k][tcol * 8 + 4]);
            float ra[8] = {ra0.x, ra0.y, ra0.z, ra0.w,
                           ra1.x, ra1.y, ra1.z, ra1.w};
            float rb[8] = {rb0.x, rb0.y, rb0.z, rb0.w,
                           rb1.x, rb1.y, rb1.z, rb1.w};
#pragma unroll
            for (int i = 0; i < 8; i++)
#pragma unroll
                for (int j = 0; j < 8; j++)
                    acc[i][j] = fmaf(ra[i], rb[j], acc[i][j]);
        }

        // chunk boundary every 4 tiles (KCHUNK=64): Neumaier fold
        if ((t & 3) == 3) {
#pragma unroll
            for (int i = 0; i < 8; i++)
#pragma unroll
                for (int j = 0; j < 8; j++) {
                    neumaier_add(sum[i][j], comp[i][j], acc[i][j]);
                    acc[i][j] = 0.f;
                }
        }

        // stage prefetched tile into the other buffer
        if (t + 1 < NT) {
            const int nb = buf ^ 1;
            As[nb][aCol + 0][aRow] = a0.x;  As[nb][aCol + 1][aRow] = a0.y;
            As[nb][aCol + 2][aRow] = a0.z;  As[nb][aCol + 3][aRow] = a0.w;
            As[nb][aCol + 4][aRow] = a1.x;  As[nb][aCol + 5][aRow] = a1.y;
            As[nb][aCol + 6][aRow] = a1.z;  As[nb][aCol + 7][aRow] = a1.w;
            *(float4*)(&Bs[nb][bRow][bCol])     = b0;
            *(float4*)(&Bs[nb][bRow][bCol + 4]) = b1;
            __syncthreads();
        }
    }

    const int cbase = blockIdx.x * BN + tcol * 8;
    float bl[8];
#pragma unroll
    for (int j = 0; j < 8; j++) bl[j] = bias[cbase + j];

#pragma unroll
    for (int i = 0; i < 8; i++) {
        size_t row = (size_t)blockIdx.y * BM + trow * 8 + i;
        float* Cr = C + row * D_SAE + cbase;
        float4 v0, v1;
        v0.x = __fadd_rn(__fadd_rn(sum[i][0], comp[i][0]), bl[0]);
        v0.y = __fadd_rn(__fadd_rn(sum[i][1], comp[i][1]), bl[1]);
        v0.z = __fadd_rn(__fadd_rn(sum[i][2], comp[i][2]), bl[2]);
        v0.w = __fadd_rn(__fadd_rn(sum[i][3], comp[i][3]), bl[3]);
        v1.x = __fadd_rn(__fadd_rn(sum[i][4], comp[i][4]), bl[4]);
        v1.y = __fadd_rn(__fadd_rn(sum[i][5], comp[i][5]), bl[5]);
        v1.z = __fadd_rn(__fadd_rn(sum[i][6], comp[i][6]), bl[6]);
        v1.w = __fadd_rn(__fadd_rn(sum[i][7], comp[i][7]), bl[7]);
        *(float4*)(Cr)     = v0;
        *(float4*)(Cr + 4) = v1;
    }
}

// ============================================================================
// Kernel 2: per-token top-64 of relu(pre) via exact 4-pass radix select on
// fp32 bit patterns (nonneg floats are uint-order monotone). Deterministic,
// lowest-index-first among equal values at the threshold (matches
// jax.lax.top_k stability). Writes compact (val, idx) to scratch and scatters
// into z (z pre-zeroed by memset). One block per token; row staged in SMEM.
// ============================================================================
__global__ void topk_kernel(const float* __restrict__ pre,
                            float* __restrict__ z)
{
    extern __shared__ unsigned sdata[];   // D_SAE uints = 128 KB
    __shared__ int hist[256];
    __shared__ int s_scan[256];
    __shared__ unsigned s_prefix;
    __shared__ int s_need;

    const int tid = threadIdx.x;          // blockDim.x == 256
    const int n   = blockIdx.x;
    const float* row = pre + (size_t)n * D_SAE;

    for (int i = tid; i < D_SAE; i += 256) {
        float v = row[i];
        sdata[i] = (v > 0.f) ? __float_as_uint(v) : 0u;
    }
    if (tid < KTOP) {
        g_vals[n * KTOP + tid] = 0.f;
        g_idx [n * KTOP + tid] = 0;
    }
    __syncthreads();

    unsigned prefix = 0;
    int need = KTOP;
    for (int shift = 24; shift >= 0; shift -= 8) {
        hist[tid] = 0;
        __syncthreads();
        for (int i = tid; i < D_SAE; i += 256) {
            unsigned x = sdata[i];
            if (x == 0u) continue;
            bool match = (shift == 24) ||
                         ((x >> (shift + 8)) == (prefix >> (shift + 8)));
            if (match) atomicAdd(&hist[(x >> shift) & 255], 1);
        }
        __syncthreads();
        if (tid == 0) {
            int total = 0;
            for (int i = 0; i < 256; i++) total += hist[i];
            int nd = need;
            if (total < nd) nd = total;
            if (nd > 0) {
                int cum = 0, b = 0;
                for (int i = 255; i >= 0; i--) {
                    if (cum + hist[i] >= nd) { b = i; break; }
                    cum += hist[i];
                }
                s_prefix = prefix | ((unsigned)b << shift);
                s_need   = nd - cum;
            } else {
                s_prefix = 0xFFFFFFFFu;
                s_need   = 0;
            }
        }
        __syncthreads();
        prefix = s_prefix;
        need   = s_need;
    }
    const unsigned T = prefix;
    const int needEq = need;

    const int start = tid * (D_SAE / 256);
    int cgt = 0, ceq = 0;
    for (int j = 0; j < D_SAE / 256; j++) {
        unsigned x = sdata[start + j];
        cgt += (x > T);
        ceq += (x == T);
    }

    s_scan[tid] = cgt;
    __syncthreads();
    for (int off = 1; off < 256; off <<= 1) {
        int v = (tid >= off) ? s_scan[tid - off] : 0;
        __syncthreads();
        s_scan[tid] += v;
        __syncthreads();
    }
    const int gtEx    = s_scan[tid] - cgt;
    const int totalGt = s_scan[255];
    __syncthreads();

    s_scan[tid] = ceq;
    __syncthreads();
    for (int off = 1; off < 256; off <<= 1) {
        int v = (tid >= off) ? s_scan[tid - off] : 0;
        __syncthreads();
        s_scan[tid] += v;
        __syncthreads();
    }
    const int eqEx = s_scan[tid] - ceq;

    int g = gtEx, e = eqEx;
    for (int j = 0; j < D_SAE / 256; j++) {
        unsigned x = sdata[start + j];
        int slot = -1;
        if (x > T) {
            slot = g++;
        } else if (x == T) {
            int r = e++;
            if (r < needEq) slot = totalGt + r;
        }
        if (slot >= 0) {
            int fi = start + j;
            float v = __uint_as_float(x);
            g_vals[n * KTOP + slot] = v;
            g_idx [n * KTOP + slot] = fi;
            z[(size_t)n * D_SAE + fi] = v;
        }
    }
}

// ============================================================================
// Kernel 3: sparse decode  x_hat[n] = sum_k v_k * W_dec[idx_k, :] + b_dec
// ============================================================================
__global__ __launch_bounds__(256)
void decode_kernel(const float* __restrict__ Wdec,
                   const float* __restrict__ bdec,
                   float* __restrict__ xhat)
{
    __shared__ float sv[KTOP];
    __shared__ int   si[KTOP];
    const int n = blockIdx.x, tid = threadIdx.x;
    if (tid < KTOP) {
        sv[tid] = g_vals[n * KTOP + tid];
        si[tid] = g_idx [n * KTOP + tid];
    }
    __syncthreads();

    float acc[8];
#pragma unroll
    for (int j = 0; j < 8; j++) acc[j] = bdec[tid + j * 256];

    for (int k = 0; k < KTOP; k++) {
        float v = sv[k];
        const float* wr = Wdec + (size_t)si[k] * D_MODEL;
#pragma unroll
        for (int j = 0; j < 8; j++)
            acc[j] = fmaf(v, wr[tid + j * 256], acc[j]);
    }

    float* orow = xhat + (size_t)n * D_MODEL;
#pragma unroll
    for (int j = 0; j < 8; j++) orow[tid + j * 256] = acc[j];
}

// ============================================================================
// Launch: out = [x_hat | z | pre] (reference return order), all fp32.
// Graph-capturable: kernels + one async memset, no sync, no allocation.
// ============================================================================
extern "C" void kernel_launch(void* const* d_in, const int* in_sizes, int n_in,
                              void* d_out, int out_size)
{
    (void)in_sizes; (void)n_in; (void)out_size;
    const float* x     = (const float*)d_in[0];
    const float* W_enc = (const float*)d_in[1];
    const float* b_enc = (const float*)d_in[2];
    const float* W_dec = (const float*)d_in[3];
    const float* b_dec = (const float*)d_in[4];

    float* out  = (float*)d_out;
    float* xhat = out;
    float* z    = out + (size_t)N_TOK * D_MODEL;
    float* pre  = z   + (size_t)N_TOK * D_SAE;

    cudaMemsetAsync(z, 0, (size_t)N_TOK * D_SAE * sizeof(float), 0);

    dim3 gemm_grid(D_SAE / BN, N_TOK / BM);
    encode_gemm<<<gemm_grid, 256>>>(x, W_enc, b_enc, pre);

    cudaFuncSetAttribute(topk_kernel,
                         cudaFuncAttributeMaxDynamicSharedMemorySize,
                         D_SAE * (int)sizeof(unsigned));
    topk_kernel<<<N_TOK, 256, D_SAE * sizeof(unsigned)>>>(pre, z);

    decode_kernel<<<N_TOK, 256>>>(W_dec, b_dec, xhat);
}

// round 12
// speedup vs baseline: 1.3667x; 1.3281x over previous
#include <cuda_runtime.h>
#include <cuda_bf16.h>
#include <cstdint>

// Problem constants (fixed shapes for TopKSAE_128849019036)
#define N_TOK   4096
#define D_MODEL 2048
#define D_SAE   32768
#define KTOP    64

// ---------------------------------------------------------------------------
// Device-global scratch (sanctioned; no dynamic allocation).
// bf16x3 split operands:
//   g_XA[p][m*D_MODEL + k] = p-th bf16 component of x[m][k]       (K-major)
//   g_WB[p][n*D_MODEL + k] = p-th bf16 component of W_enc[k][n]   (K-major)
// ---------------------------------------------------------------------------
__device__ __nv_bfloat16 g_XA0[(size_t)N_TOK * D_MODEL];
__device__ __nv_bfloat16 g_XA1[(size_t)N_TOK * D_MODEL];
__device__ __nv_bfloat16 g_XA2[(size_t)N_TOK * D_MODEL];
__device__ __nv_bfloat16 g_WB0[(size_t)D_SAE * D_MODEL];
__device__ __nv_bfloat16 g_WB1[(size_t)D_SAE * D_MODEL];
__device__ __nv_bfloat16 g_WB2[(size_t)D_SAE * D_MODEL];
__device__ float g_vals[N_TOK * KTOP];
__device__ int   g_idx [N_TOK * KTOP];

__device__ __forceinline__ uint32_t smem_u32(const void* p) {
    uint32_t a;
    asm("{ .reg .u64 t; cvta.to.shared.u64 t, %1; cvt.u32.u64 %0, t; }"
        : "=r"(a) : "l"(p));
    return a;
}

// ---------------------------------------------------------------------------
// exact 3-way bf16 split:  v = h0 + h1 + h2 + O(2^-27 v)
// ---------------------------------------------------------------------------
__device__ __forceinline__ void split3(float v, unsigned short& h0,
                                       unsigned short& h1, unsigned short& h2) {
    __nv_bfloat16 b0 = __float2bfloat16(v);
    float r1 = __fsub_rn(v, __bfloat162float(b0));
    __nv_bfloat16 b1 = __float2bfloat16(r1);
    float r2 = __fsub_rn(r1, __bfloat162float(b1));
    __nv_bfloat16 b2 = __float2bfloat16(r2);
    h0 = *reinterpret_cast<unsigned short*>(&b0);
    h1 = *reinterpret_cast<unsigned short*>(&b1);
    h2 = *reinterpret_cast<unsigned short*>(&b2);
}

// ===========================================================================
// Pre-pass 1: split x -> g_XA0/1/2 (same [M,K] layout)
// ===========================================================================
__global__ __launch_bounds__(256)
void split_x_kernel(const float* __restrict__ x)
{
    size_t gid = (size_t)blockIdx.x * 256 + threadIdx.x;  // over float4s
    float4 v = ((const float4*)x)[gid];
    ushort4 o0, o1, o2;
    split3(v.x, o0.x, o1.x, o2.x);
    split3(v.y, o0.y, o1.y, o2.y);
    split3(v.z, o0.z, o1.z, o2.z);
    split3(v.w, o0.w, o1.w, o2.w);
    ((ushort4*)g_XA0)[gid] = o0;
    ((ushort4*)g_XA1)[gid] = o1;
    ((ushort4*)g_XA2)[gid] = o2;
}

// ===========================================================================
// Pre-pass 2: transpose + split W_enc [K, N] -> g_WB0/1/2 [N, K]
// ===========================================================================
__global__ __launch_bounds__(256)
void split_w_kernel(const float* __restrict__ W)
{
    __shared__ float tile[32][33];
    const int kt = blockIdx.x * 32, nt = blockIdx.y * 32;
    const int tid = threadIdx.x;
    const int tr = tid >> 5, tc = tid & 31;
#pragma unroll
    for (int i = 0; i < 4; i++) {
        int kk = tr + i * 8;
        tile[kk][tc] = W[(size_t)(kt + kk) * D_SAE + nt + tc];
    }
    __syncthreads();
    const int nr = tid >> 3;          // 0..31
    const int kc = (tid & 7) * 4;     // 0..28
    ushort4 o0, o1, o2;
    split3(tile[kc + 0][nr], o0.x, o1.x, o2.x);
    split3(tile[kc + 1][nr], o0.y, o1.y, o2.y);
    split3(tile[kc + 2][nr], o0.z, o1.z, o2.z);
    split3(tile[kc + 3][nr], o0.w, o1.w, o2.w);
    size_t off = ((size_t)(nt + nr) * D_MODEL + kt + kc) >> 2;  // in ushort4
    ((ushort4*)g_WB0)[off] = o0;
    ((ushort4*)g_WB1)[off] = o1;
    ((ushort4*)g_WB2)[off] = o2;
}

// ===========================================================================
// Encode GEMM via baseline mma.sync (legacy HMMA pipe; tcgen05 is blocked by
// the harness's compute_103 virtual arch).
//
// pre[4096, 32768] = x @ W_enc + b_enc, fp32-accurate via bf16x3 splits and
// 6 cross products (i+j<=2; dropped terms ~2^-27). mma fp32 accumulators,
// chunked at K=256 with fp32 register folds -> eps ~2-3e-7.
//
// CTA tile 128x128, BK=32, 256 threads (8 warps, warp tile m32 x n64).
// Double-buffered smem via cp.async; padded row stride 40 halves (80B) makes
// ldmatrix 8-row access conflict-free (offsets mod 128B all distinct).
// ===========================================================================
#define BK      32
#define TS      40                    // padded tile row stride, in halves
#define TILE_B  (128 * TS * 2)        // 10240 B per operand tile
#define STAGE_B (6 * TILE_B)          // 61440 B per stage (A0..2, B0..2)
#define SMEM_REQ (2 * STAGE_B)        // 122880 B
#define NSLAB   (D_MODEL / BK)        // 64

__device__ __forceinline__ void mma16816(float* d, const uint32_t* a,
                                         const uint32_t* b) {
    asm volatile(
        "mma.sync.aligned.m16n8k16.row.col.f32.bf16.bf16.f32 "
        "{%0,%1,%2,%3}, {%4,%5,%6,%7}, {%8,%9}, {%0,%1,%2,%3};"
        : "+f"(d[0]), "+f"(d[1]), "+f"(d[2]), "+f"(d[3])
        : "r"(a[0]), "r"(a[1]), "r"(a[2]), "r"(a[3]), "r"(b[0]), "r"(b[1]));
}

__global__ __launch_bounds__(256, 1)
void encode_gemm_mma(const float* __restrict__ bias, float* __restrict__ C)
{
    extern __shared__ char smem[];
    const uint32_t sbase = smem_u32(smem);
    const int tid  = threadIdx.x, wid = tid >> 5, lane = tid & 31;
    const int mtile = blockIdx.x, ntile = blockIdx.y;

    const __nv_bfloat16* src[6] = {
        g_XA0 + (size_t)mtile * 128 * D_MODEL,
        g_XA1 + (size_t)mtile * 128 * D_MODEL,
        g_XA2 + (size_t)mtile * 128 * D_MODEL,
        g_WB0 + (size_t)ntile * 128 * D_MODEL,
        g_WB1 + (size_t)ntile * 128 * D_MODEL,
        g_WB2 + (size_t)ntile * 128 * D_MODEL };

    // ---- cp.async staging of one K-slab (6 tiles x 128 rows x 64B) ----
    auto issue_slab = [&](int t) {
        const uint32_t dstbase = sbase + (uint32_t)(t & 1) * STAGE_B;
        const size_t ks = (size_t)t * BK;
#pragma unroll
        for (int u = 0; u < 12; u++) {
            const int tile = u >> 1;                 // compile-time constant
            const int op  = ((u & 1) << 8) + tid;    // 0..511
            const int r   = op >> 2, seg = op & 3;
            const __nv_bfloat16* s = src[tile] + (size_t)r * D_MODEL + ks + seg * 8;
            const uint32_t d = dstbase + tile * TILE_B + r * (TS * 2) + seg * 16;
            asm volatile("cp.async.cg.shared.global [%0], [%1], 16;"
                         :: "r"(d), "l"(s) : "memory");
        }
        asm volatile("cp.async.commit_group;" ::: "memory");
    };

    float acc[2][8][4], sum[2][8][4];
#pragma unroll
    for (int mi = 0; mi < 2; mi++)
#pragma unroll
        for (int nt = 0; nt < 8; nt++)
#pragma unroll
            for (int q = 0; q < 4; q++) {
                acc[mi][nt][q] = 0.f; sum[mi][nt][q] = 0.f;
            }

    const int wm = (wid & 3) * 32;    // warp M offset in CTA tile
    const int wn = (wid >> 2) * 64;   // warp N offset
    const int lrow = lane & 15, lcol = lane >> 4;

    issue_slab(0);

    for (int t = 0; t < NSLAB; t++) {
        if (t + 1 < NSLAB) {
            issue_slab(t + 1);
            asm volatile("cp.async.wait_group 1;" ::: "memory");
        } else {
            asm volatile("cp.async.wait_group 0;" ::: "memory");
        }
        __syncthreads();

        const uint32_t sb = sbase + (uint32_t)(t & 1) * STAGE_B;
#pragma unroll
        for (int kstep = 0; kstep < 2; kstep++) {
            // A fragments for all 3 splits (m32 x k16 each)
            uint32_t a[3][2][4];
#pragma unroll
            for (int ap = 0; ap < 3; ap++)
#pragma unroll
                for (int mi = 0; mi < 2; mi++) {
                    const uint32_t addr = sb + ap * TILE_B +
                        (wm + mi * 16 + lrow) * (TS * 2) + kstep * 32 + lcol * 16;
                    asm volatile(
                        "ldmatrix.sync.aligned.m8n8.x4.shared.b16 {%0,%1,%2,%3}, [%4];"
                        : "=r"(a[ap][mi][0]), "=r"(a[ap][mi][1]),
                          "=r"(a[ap][mi][2]), "=r"(a[ap][mi][3])
                        : "r"(addr));
                }
#pragma unroll
            for (int bp = 0; bp < 3; bp++) {
                // B fragments: n64 x k16 (8 n8-tiles)
                uint32_t bf[8][2];
#pragma unroll
                for (int nb = 0; nb < 4; nb++) {
                    uint32_t r0, r1, r2, r3;
                    const uint32_t addr = sb + (3 + bp) * TILE_B +
                        (wn + nb * 16 + lrow) * (TS * 2) + kstep * 32 + lcol * 16;
                    asm volatile(
                        "ldmatrix.sync.aligned.m8n8.x4.shared.b16 {%0,%1,%2,%3}, [%4];"
                        : "=r"(r0), "=r"(r1), "=r"(r2), "=r"(r3)
                        : "r"(addr));
                    bf[2 * nb][0] = r0;  bf[2 * nb][1] = r2;
                    bf[2 * nb + 1][0] = r1;  bf[2 * nb + 1][1] = r3;
                }
#pragma unroll
                for (int ap = 0; ap < 3; ap++) {
                    if (ap + bp <= 2) {   // 6 products: i+j<=2
#pragma unroll
                        for (int mi = 0; mi < 2; mi++)
#pragma unroll
                            for (int nt = 0; nt < 8; nt++)
                                mma16816(acc[mi][nt], a[ap][mi], bf[nt]);
                    }
                }
            }
        }
        __syncthreads();

        // chunk fold every 8 slabs (K=256)
        if ((t & 7) == 7) {
#pragma unroll
            for (int mi = 0; mi < 2; mi++)
#pragma unroll
                for (int nt = 0; nt < 8; nt++)
#pragma unroll
                    for (int q = 0; q < 4; q++) {
                        sum[mi][nt][q] = __fadd_rn(sum[mi][nt][q], acc[mi][nt][q]);
                        acc[mi][nt][q] = 0.f;
                    }
        }
    }

    // ---- epilogue: + bias, store (d0,d1 -> row r; d2,d3 -> row r+8) ----
#pragma unroll
    for (int mi = 0; mi < 2; mi++)
#pragma unroll
        for (int nt = 0; nt < 8; nt++) {
            const int row = mtile * 128 + wm + mi * 16 + (lane >> 2);
            const int col = ntile * 128 + wn + nt * 8 + (lane & 3) * 2;
            const float b0 = bias[col], b1 = bias[col + 1];
            float2 v0, v1;
            v0.x = __fadd_rn(sum[mi][nt][0], b0);
            v0.y = __fadd_rn(sum[mi][nt][1], b1);
            v1.x = __fadd_rn(sum[mi][nt][2], b0);
            v1.y = __fadd_rn(sum[mi][nt][3], b1);
            *(float2*)(C + (size_t)row * D_SAE + col)       = v0;
            *(float2*)(C + (size_t)(row + 8) * D_SAE + col) = v1;
        }
}

// ============================================================================
// Top-64 of relu(pre) per token: exact 4-pass radix select on fp32 bit
// patterns, deterministic lowest-index-first ties (matches jax.lax.top_k).
// ============================================================================
__global__ void topk_kernel(const float* __restrict__ pre,
                            float* __restrict__ z)
{
    extern __shared__ unsigned sdata[];   // D_SAE uints = 128 KB
    __shared__ int hist[256];
    __shared__ int s_scan[256];
    __shared__ unsigned s_prefix;
    __shared__ int s_need;

    const int tid = threadIdx.x;
    const int n   = blockIdx.x;
    const float* row = pre + (size_t)n * D_SAE;

    for (int i = tid; i < D_SAE; i += 256) {
        float v = row[i];
        sdata[i] = (v > 0.f) ? __float_as_uint(v) : 0u;
    }
    if (tid < KTOP) {
        g_vals[n * KTOP + tid] = 0.f;
        g_idx [n * KTOP + tid] = 0;
    }
    __syncthreads();

    unsigned prefix = 0;
    int need = KTOP;
    for (int shift = 24; shift >= 0; shift -= 8) {
        hist[tid] = 0;
        __syncthreads();
        for (int i = tid; i < D_SAE; i += 256) {
            unsigned x = sdata[i];
            if (x == 0u) continue;
            bool match = (shift == 24) ||
                         ((x >> (shift + 8)) == (prefix >> (shift + 8)));
            if (match) atomicAdd(&hist[(x >> shift) & 255], 1);
        }
        __syncthreads();
        if (tid == 0) {
            int total = 0;
            for (int i = 0; i < 256; i++) total += hist[i];
            int nd = need;
            if (total < nd) nd = total;
            if (nd > 0) {
                int cum = 0, b = 0;
                for (int i = 255; i >= 0; i--) {
                    if (cum + hist[i] >= nd) { b = i; break; }
                    cum += hist[i];
                }
                s_prefix = prefix | ((unsigned)b << shift);
                s_need   = nd - cum;
            } else {
                s_prefix = 0xFFFFFFFFu;
                s_need   = 0;
            }
        }
        __syncthreads();
        prefix = s_prefix;
        need   = s_need;
    }
    const unsigned T = prefix;
    const int needEq = need;

    const int start = tid * (D_SAE / 256);
    int cgt = 0, ceq = 0;
    for (int j = 0; j < D_SAE / 256; j++) {
        unsigned x = sdata[start + j];
        cgt += (x > T);
        ceq += (x == T);
    }

    s_scan[tid] = cgt;
    __syncthreads();
    for (int off = 1; off < 256; off <<= 1) {
        int v = (tid >= off) ? s_scan[tid - off] : 0;
        __syncthreads();
        s_scan[tid] += v;
        __syncthreads();
    }
    const int gtEx    = s_scan[tid] - cgt;
    const int totalGt = s_scan[255];
    __syncthreads();

    s_scan[tid] = ceq;
    __syncthreads();
    for (int off = 1; off < 256; off <<= 1) {
        int v = (tid >= off) ? s_scan[tid - off] : 0;
        __syncthreads();
        s_scan[tid] += v;
        __syncthreads();
    }
    const int eqEx = s_scan[tid] - ceq;

    int g = gtEx, e = eqEx;
    for (int j = 0; j < D_SAE / 256; j++) {
        unsigned x = sdata[start + j];
        int slot = -1;
        if (x > T) {
            slot = g++;
        } else if (x == T) {
            int r = e++;
            if (r < needEq) slot = totalGt + r;
        }
        if (slot >= 0) {
            int fi = start + j;
            float v = __uint_as_float(x);
            g_vals[n * KTOP + slot] = v;
            g_idx [n * KTOP + slot] = fi;
            z[(size_t)n * D_SAE + fi] = v;
        }
    }
}

// ============================================================================
// Sparse decode  x_hat[n] = sum_k v_k * W_dec[idx_k, :] + b_dec
// ============================================================================
__global__ __launch_bounds__(256)
void decode_kernel(const float* __restrict__ Wdec,
                   const float* __restrict__ bdec,
                   float* __restrict__ xhat)
{
    __shared__ float sv[KTOP];
    __shared__ int   si[KTOP];
    const int n = blockIdx.x, tid = threadIdx.x;
    if (tid < KTOP) {
        sv[tid] = g_vals[n * KTOP + tid];
        si[tid] = g_idx [n * KTOP + tid];
    }
    __syncthreads();

    float acc[8];
#pragma unroll
    for (int j = 0; j < 8; j++) acc[j] = bdec[tid + j * 256];

    for (int k = 0; k < KTOP; k++) {
        float v = sv[k];
        const float* wr = Wdec + (size_t)si[k] * D_MODEL;
#pragma unroll
        for (int j = 0; j < 8; j++)
            acc[j] = fmaf(v, wr[tid + j * 256], acc[j]);
    }

    float* orow = xhat + (size_t)n * D_MODEL;
#pragma unroll
    for (int j = 0; j < 8; j++) orow[tid + j * 256] = acc[j];
}

// ============================================================================
// Launch: out = [x_hat | z | pre], all fp32. Graph-capturable.
// ============================================================================
extern "C" void kernel_launch(void* const* d_in, const int* in_sizes, int n_in,
                              void* d_out, int out_size)
{
    (void)in_sizes; (void)n_in; (void)out_size;
    const float* x     = (const float*)d_in[0];
    const float* W_enc = (const float*)d_in[1];
    const float* b_enc = (const float*)d_in[2];
    const float* W_dec = (const float*)d_in[3];
    const float* b_dec = (const float*)d_in[4];

    float* out  = (float*)d_out;
    float* xhat = out;
    float* z    = out + (size_t)N_TOK * D_MODEL;
    float* pre  = z   + (size_t)N_TOK * D_SAE;

    cudaMemsetAsync(z, 0, (size_t)N_TOK * D_SAE * sizeof(float), 0);

    // pre-pass: bf16x3 splits
    split_x_kernel<<<(N_TOK * D_MODEL / 4) / 256, 256>>>(x);
    split_w_kernel<<<dim3(D_MODEL / 32, D_SAE / 32), 256>>>(W_enc);

    // mma.sync encode GEMM (grid x = M-tiles so each wave shares B via L2)
    cudaFuncSetAttribute(encode_gemm_mma,
                         cudaFuncAttributeMaxDynamicSharedMemorySize, SMEM_REQ);
    encode_gemm_mma<<<dim3(N_TOK / 128, D_SAE / 128), 256, SMEM_REQ>>>(b_enc, pre);

    cudaFuncSetAttribute(topk_kernel,
                         cudaFuncAttributeMaxDynamicSharedMemorySize,
                         D_SAE * (int)sizeof(unsigned));
    topk_kernel<<<N_TOK, 256, D_SAE * sizeof(unsigned)>>>(pre, z);

    decode_kernel<<<N_TOK, 256>>>(W_dec, b_dec, xhat);
}

// round 13
// speedup vs baseline: 1.5758x; 1.1530x over previous
#include <cuda_runtime.h>
#include <cuda_bf16.h>
#include <cstdint>

// Problem constants (fixed shapes for TopKSAE_128849019036)
#define N_TOK   4096
#define D_MODEL 2048
#define D_SAE   32768
#define KTOP    64

// ---------------------------------------------------------------------------
// Device-global scratch (sanctioned; no dynamic allocation).
// bf16x3 split operands:
//   g_XA[p][m*D_MODEL + k] = p-th bf16 component of x[m][k]       (K-major)
//   g_WB[p][n*D_MODEL + k] = p-th bf16 component of W_enc[k][n]   (K-major)
// ---------------------------------------------------------------------------
__device__ __nv_bfloat16 g_XA0[(size_t)N_TOK * D_MODEL];
__device__ __nv_bfloat16 g_XA1[(size_t)N_TOK * D_MODEL];
__device__ __nv_bfloat16 g_XA2[(size_t)N_TOK * D_MODEL];
__device__ __nv_bfloat16 g_WB0[(size_t)D_SAE * D_MODEL];
__device__ __nv_bfloat16 g_WB1[(size_t)D_SAE * D_MODEL];
__device__ __nv_bfloat16 g_WB2[(size_t)D_SAE * D_MODEL];
__device__ float g_vals[N_TOK * KTOP];
__device__ int   g_idx [N_TOK * KTOP];

__device__ __forceinline__ uint32_t smem_u32(const void* p) {
    uint32_t a;
    asm("{ .reg .u64 t; cvta.to.shared.u64 t, %1; cvt.u32.u64 %0, t; }"
        : "=r"(a) : "l"(p));
    return a;
}

// ---------------------------------------------------------------------------
// exact 3-way bf16 split:  v = h0 + h1 + h2 + O(2^-27 v)
// ---------------------------------------------------------------------------
__device__ __forceinline__ void split3(float v, unsigned short& h0,
                                       unsigned short& h1, unsigned short& h2) {
    __nv_bfloat16 b0 = __float2bfloat16(v);
    float r1 = __fsub_rn(v, __bfloat162float(b0));
    __nv_bfloat16 b1 = __float2bfloat16(r1);
    float r2 = __fsub_rn(r1, __bfloat162float(b1));
    __nv_bfloat16 b2 = __float2bfloat16(r2);
    h0 = *reinterpret_cast<unsigned short*>(&b0);
    h1 = *reinterpret_cast<unsigned short*>(&b1);
    h2 = *reinterpret_cast<unsigned short*>(&b2);
}

// ===========================================================================
// Pre-pass 1: split x -> g_XA0/1/2 (same [M,K] layout)
// ===========================================================================
__global__ __launch_bounds__(256)
void split_x_kernel(const float* __restrict__ x)
{
    size_t gid = (size_t)blockIdx.x * 256 + threadIdx.x;  // over float4s
    float4 v = ((const float4*)x)[gid];
    ushort4 o0, o1, o2;
    split3(v.x, o0.x, o1.x, o2.x);
    split3(v.y, o0.y, o1.y, o2.y);
    split3(v.z, o0.z, o1.z, o2.z);
    split3(v.w, o0.w, o1.w, o2.w);
    ((ushort4*)g_XA0)[gid] = o0;
    ((ushort4*)g_XA1)[gid] = o1;
    ((ushort4*)g_XA2)[gid] = o2;
}

// ===========================================================================
// Pre-pass 2: transpose + split W_enc [K, N] -> g_WB0/1/2 [N, K]
// ===========================================================================
__global__ __launch_bounds__(256)
void split_w_kernel(const float* __restrict__ W)
{
    __shared__ float tile[32][33];
    const int kt = blockIdx.x * 32, nt = blockIdx.y * 32;
    const int tid = threadIdx.x;
    const int tr = tid >> 5, tc = tid & 31;
#pragma unroll
    for (int i = 0; i < 4; i++) {
        int kk = tr + i * 8;
        tile[kk][tc] = W[(size_t)(kt + kk) * D_SAE + nt + tc];
    }
    __syncthreads();
    const int nr = tid >> 3;          // 0..31
    const int kc = (tid & 7) * 4;     // 0..28
    ushort4 o0, o1, o2;
    split3(tile[kc + 0][nr], o0.x, o1.x, o2.x);
    split3(tile[kc + 1][nr], o0.y, o1.y, o2.y);
    split3(tile[kc + 2][nr], o0.z, o1.z, o2.z);
    split3(tile[kc + 3][nr], o0.w, o1.w, o2.w);
    size_t off = ((size_t)(nt + nr) * D_MODEL + kt + kc) >> 2;  // in ushort4
    ((ushort4*)g_WB0)[off] = o0;
    ((ushort4*)g_WB1)[off] = o1;
    ((ushort4*)g_WB2)[off] = o2;
}

// ===========================================================================
// Encode GEMM via baseline mma.sync (legacy HMMA pipe; tcgen05 blocked by the
// harness's compute_103 virtual arch). NUMERICS FROZEN — passed R12 with
// rel_err 1.86e-6 (zero top-k flips); do not change summation order.
// ===========================================================================
#define BK      32
#define TS      40                    // padded tile row stride, in halves
#define TILE_B  (128 * TS * 2)        // 10240 B per operand tile
#define STAGE_B (6 * TILE_B)          // 61440 B per stage (A0..2, B0..2)
#define SMEM_REQ (2 * STAGE_B)        // 122880 B
#define NSLAB   (D_MODEL / BK)        // 64

__device__ __forceinline__ void mma16816(float* d, const uint32_t* a,
                                         const uint32_t* b) {
    asm volatile(
        "mma.sync.aligned.m16n8k16.row.col.f32.bf16.bf16.f32 "
        "{%0,%1,%2,%3}, {%4,%5,%6,%7}, {%8,%9}, {%0,%1,%2,%3};"
        : "+f"(d[0]), "+f"(d[1]), "+f"(d[2]), "+f"(d[3])
        : "r"(a[0]), "r"(a[1]), "r"(a[2]), "r"(a[3]), "r"(b[0]), "r"(b[1]));
}

__global__ __launch_bounds__(256, 1)
void encode_gemm_mma(const float* __restrict__ bias, float* __restrict__ C)
{
    extern __shared__ char smem[];
    const uint32_t sbase = smem_u32(smem);
    const int tid  = threadIdx.x, wid = tid >> 5, lane = tid & 31;
    const int mtile = blockIdx.x, ntile = blockIdx.y;

    const __nv_bfloat16* src[6] = {
        g_XA0 + (size_t)mtile * 128 * D_MODEL,
        g_XA1 + (size_t)mtile * 128 * D_MODEL,
        g_XA2 + (size_t)mtile * 128 * D_MODEL,
        g_WB0 + (size_t)ntile * 128 * D_MODEL,
        g_WB1 + (size_t)ntile * 128 * D_MODEL,
        g_WB2 + (size_t)ntile * 128 * D_MODEL };

    auto issue_slab = [&](int t) {
        const uint32_t dstbase = sbase + (uint32_t)(t & 1) * STAGE_B;
        const size_t ks = (size_t)t * BK;
#pragma unroll
        for (int u = 0; u < 12; u++) {
            const int tile = u >> 1;
            const int op  = ((u & 1) << 8) + tid;    // 0..511
            const int r   = op >> 2, seg = op & 3;
            const __nv_bfloat16* s = src[tile] + (size_t)r * D_MODEL + ks + seg * 8;
            const uint32_t d = dstbase + tile * TILE_B + r * (TS * 2) + seg * 16;
            asm volatile("cp.async.cg.shared.global [%0], [%1], 16;"
                         :: "r"(d), "l"(s) : "memory");
        }
        asm volatile("cp.async.commit_group;" ::: "memory");
    };

    float acc[2][8][4], sum[2][8][4];
#pragma unroll
    for (int mi = 0; mi < 2; mi++)
#pragma unroll
        for (int nt = 0; nt < 8; nt++)
#pragma unroll
            for (int q = 0; q < 4; q++) {
                acc[mi][nt][q] = 0.f; sum[mi][nt][q] = 0.f;
            }

    const int wm = (wid & 3) * 32;
    const int wn = (wid >> 2) * 64;
    const int lrow = lane & 15, lcol = lane >> 4;

    issue_slab(0);

    for (int t = 0; t < NSLAB; t++) {
        if (t + 1 < NSLAB) {
            issue_slab(t + 1);
            asm volatile("cp.async.wait_group 1;" ::: "memory");
        } else {
            asm volatile("cp.async.wait_group 0;" ::: "memory");
        }
        __syncthreads();

        const uint32_t sb = sbase + (uint32_t)(t & 1) * STAGE_B;
#pragma unroll
        for (int kstep = 0; kstep < 2; kstep++) {
            uint32_t a[3][2][4];
#pragma unroll
            for (int ap = 0; ap < 3; ap++)
#pragma unroll
                for (int mi = 0; mi < 2; mi++) {
                    const uint32_t addr = sb + ap * TILE_B +
                        (wm + mi * 16 + lrow) * (TS * 2) + kstep * 32 + lcol * 16;
                    asm volatile(
                        "ldmatrix.sync.aligned.m8n8.x4.shared.b16 {%0,%1,%2,%3}, [%4];"
                        : "=r"(a[ap][mi][0]), "=r"(a[ap][mi][1]),
                          "=r"(a[ap][mi][2]), "=r"(a[ap][mi][3])
                        : "r"(addr));
                }
#pragma unroll
            for (int bp = 0; bp < 3; bp++) {
                uint32_t bf[8][2];
#pragma unroll
                for (int nb = 0; nb < 4; nb++) {
                    uint32_t r0, r1, r2, r3;
                    const uint32_t addr = sb + (3 + bp) * TILE_B +
                        (wn + nb * 16 + lrow) * (TS * 2) + kstep * 32 + lcol * 16;
                    asm volatile(
                        "ldmatrix.sync.aligned.m8n8.x4.shared.b16 {%0,%1,%2,%3}, [%4];"
                        : "=r"(r0), "=r"(r1), "=r"(r2), "=r"(r3)
                        : "r"(addr));
                    bf[2 * nb][0] = r0;  bf[2 * nb][1] = r2;
                    bf[2 * nb + 1][0] = r1;  bf[2 * nb + 1][1] = r3;
                }
#pragma unroll
                for (int ap = 0; ap < 3; ap++) {
                    if (ap + bp <= 2) {
#pragma unroll
                        for (int mi = 0; mi < 2; mi++)
#pragma unroll
                            for (int nt = 0; nt < 8; nt++)
                                mma16816(acc[mi][nt], a[ap][mi], bf[nt]);
                    }
                }
            }
        }
        __syncthreads();

        if ((t & 7) == 7) {   // chunk fold every K=256
#pragma unroll
            for (int mi = 0; mi < 2; mi++)
#pragma unroll
                for (int nt = 0; nt < 8; nt++)
#pragma unroll
                    for (int q = 0; q < 4; q++) {
                        sum[mi][nt][q] = __fadd_rn(sum[mi][nt][q], acc[mi][nt][q]);
                        acc[mi][nt][q] = 0.f;
                    }
        }
    }

#pragma unroll
    for (int mi = 0; mi < 2; mi++)
#pragma unroll
        for (int nt = 0; nt < 8; nt++) {
            const int row = mtile * 128 + wm + mi * 16 + (lane >> 2);
            const int col = ntile * 128 + wn + nt * 8 + (lane & 3) * 2;
            const float b0 = bias[col], b1 = bias[col + 1];
            float2 v0, v1;
            v0.x = __fadd_rn(sum[mi][nt][0], b0);
            v0.y = __fadd_rn(sum[mi][nt][1], b1);
            v1.x = __fadd_rn(sum[mi][nt][2], b0);
            v1.y = __fadd_rn(sum[mi][nt][3], b1);
            *(float2*)(C + (size_t)row * D_SAE + col)       = v0;
            *(float2*)(C + (size_t)(row + 8) * D_SAE + col) = v1;
        }
}

// ============================================================================
// Top-64 of relu(pre), v2 — exact selection, identical semantics/outputs to
// the radix version (values desc, ties lowest-index, matches jax.lax.top_k),
// but ~10x cheaper:
//  1) 11-bit histogram of positive fp32 bit patterns (bits>>20; monotone),
//     2 warp-group-split copies to halve shared-atomic conflicts.
//  2) parallel suffix-scan over 2048 bins -> threshold bin B (+ total count).
//  3) second gmem pass collects candidates (bin >= B, ~82 typical) into smem;
//     exact O(c^2) rank selection by (value desc, index asc).
// smem 33 KB -> ~6 blocks/SM (vs 128 KB / 1 block/SM before).
// ============================================================================
#define NBIN 2048
#define CAND 2048

__global__ __launch_bounds__(256)
void topk_kernel(const float* __restrict__ pre, float* __restrict__ z)
{
    __shared__ int   hist[2][NBIN];
    __shared__ int   s_scan[256];
    __shared__ float cv[CAND];
    __shared__ int   ci[CAND];
    __shared__ int   s_cnt, s_B, s_K;

    const int tid = threadIdx.x;           // 256 threads
    const int n   = blockIdx.x;
    const float* row = pre + (size_t)n * D_SAE;
    const int h = (tid >> 5) & 1;          // warp-group histogram split

    for (int i = tid; i < NBIN; i += 256) { hist[0][i] = 0; hist[1][i] = 0; }
    if (tid < KTOP) { g_vals[n * KTOP + tid] = 0.f; g_idx[n * KTOP + tid] = 0; }
    if (tid == 0) s_cnt = 0;
    __syncthreads();

    // pass 1: histogram positive values by top 11 bits (monotone for v>0)
    for (int i = tid; i < D_SAE / 4; i += 256) {
        float4 v = ((const float4*)row)[i];
        if (v.x > 0.f) atomicAdd(&hist[h][__float_as_uint(v.x) >> 20], 1);
        if (v.y > 0.f) atomicAdd(&hist[h][__float_as_uint(v.y) >> 20], 1);
        if (v.z > 0.f) atomicAdd(&hist[h][__float_as_uint(v.z) >> 20], 1);
        if (v.w > 0.f) atomicAdd(&hist[h][__float_as_uint(v.w) >> 20], 1);
    }
    __syncthreads();

    // merge split histograms; per-thread partial (8 bins each)
    int tsum = 0;
#pragma unroll
    for (int b = 0; b < 8; b++) {
        const int bb = tid * 8 + b;
        const int c = hist[0][bb] + hist[1][bb];
        hist[0][bb] = c;
        tsum += c;
    }
    s_scan[tid] = tsum;
    __syncthreads();

    // inclusive suffix scan: s_scan[t] = count of bins in ranges t..255
    for (int off = 1; off < 256; off <<= 1) {
        int v = (tid + off < 256) ? s_scan[tid + off] : 0;
        __syncthreads();
        s_scan[tid] += v;
        __syncthreads();
    }
    const int total = s_scan[0];

    if (total <= KTOP) {
        if (tid == 0) { s_B = 0; s_K = total; }   // take all positives
    } else {
        const int above = (tid < 255) ? s_scan[tid + 1] : 0;
        if (s_scan[tid] >= KTOP && above < KTOP) {   // unique owner thread
            int cum = above, B = tid * 8;
#pragma unroll
            for (int b = 7; b >= 0; b--) {
                cum += hist[0][tid * 8 + b];
                if (cum >= KTOP) { B = tid * 8 + b; break; }
            }
            s_B = B; s_K = KTOP;
        }
    }
    __syncthreads();
    const unsigned B = (unsigned)s_B;
    const int Ksel = s_K;

    // pass 2: collect candidates (bin >= B). Typical count ~82; buffer 2048.
    for (int i = tid; i < D_SAE / 4; i += 256) {
        float4 v = ((const float4*)row)[i];
        const int base = 4 * i;
        if (v.x > 0.f && (__float_as_uint(v.x) >> 20) >= B) {
            int p = atomicAdd(&s_cnt, 1);
            if (p < CAND) { cv[p] = v.x; ci[p] = base; }
        }
        if (v.y > 0.f && (__float_as_uint(v.y) >> 20) >= B) {
            int p = atomicAdd(&s_cnt, 1);
            if (p < CAND) { cv[p] = v.y; ci[p] = base + 1; }
        }
        if (v.z > 0.f && (__float_as_uint(v.z) >> 20) >= B) {
            int p = atomicAdd(&s_cnt, 1);
            if (p < CAND) { cv[p] = v.z; ci[p] = base + 2; }
        }
        if (v.w > 0.f && (__float_as_uint(v.w) >> 20) >= B) {
            int p = atomicAdd(&s_cnt, 1);
            if (p < CAND) { cv[p] = v.w; ci[p] = base + 3; }
        }
    }
    __syncthreads();
    const int c = min(s_cnt, CAND);

    // exact rank selection: rank = #{q : (vq > vp) or (vq == vp and iq < ip)}
    for (int p = tid; p < c; p += 256) {
        const float vp = cv[p];
        const int   ip = ci[p];
        int rank = 0;
        for (int q = 0; q < c; q++) {
            const float vq = cv[q];
            rank += (vq > vp) || (vq == vp && ci[q] < ip);
        }
        if (rank < Ksel) {
            g_vals[n * KTOP + rank] = vp;
            g_idx [n * KTOP + rank] = ip;
            z[(size_t)n * D_SAE + ip] = vp;
        }
    }
}

// ============================================================================
// Sparse decode  x_hat[n] = sum_k v_k * W_dec[idx_k, :] + b_dec
// ============================================================================
__global__ __launch_bounds__(256)
void decode_kernel(const float* __restrict__ Wdec,
                   const float* __restrict__ bdec,
                   float* __restrict__ xhat)
{
    __shared__ float sv[KTOP];
    __shared__ int   si[KTOP];
    const int n = blockIdx.x, tid = threadIdx.x;
    if (tid < KTOP) {
        sv[tid] = g_vals[n * KTOP + tid];
        si[tid] = g_idx [n * KTOP + tid];
    }
    __syncthreads();

    float acc[8];
#pragma unroll
    for (int j = 0; j < 8; j++) acc[j] = bdec[tid + j * 256];

    for (int k = 0; k < KTOP; k++) {
        float v = sv[k];
        const float* wr = Wdec + (size_t)si[k] * D_MODEL;
#pragma unroll
        for (int j = 0; j < 8; j++)
            acc[j] = fmaf(v, wr[tid + j * 256], acc[j]);
    }

    float* orow = xhat + (size_t)n * D_MODEL;
#pragma unroll
    for (int j = 0; j < 8; j++) orow[tid + j * 256] = acc[j];
}

// ============================================================================
// Launch: out = [x_hat | z | pre], all fp32. Graph-capturable.
// ============================================================================
extern "C" void kernel_launch(void* const* d_in, const int* in_sizes, int n_in,
                              void* d_out, int out_size)
{
    (void)in_sizes; (void)n_in; (void)out_size;
    const float* x     = (const float*)d_in[0];
    const float* W_enc = (const float*)d_in[1];
    const float* b_enc = (const float*)d_in[2];
    const float* W_dec = (const float*)d_in[3];
    const float* b_dec = (const float*)d_in[4];

    float* out  = (float*)d_out;
    float* xhat = out;
    float* z    = out + (size_t)N_TOK * D_MODEL;
    float* pre  = z   + (size_t)N_TOK * D_SAE;

    cudaMemsetAsync(z, 0, (size_t)N_TOK * D_SAE * sizeof(float), 0);

    // pre-pass: bf16x3 splits
    split_x_kernel<<<(N_TOK * D_MODEL / 4) / 256, 256>>>(x);
    split_w_kernel<<<dim3(D_MODEL / 32, D_SAE / 32), 256>>>(W_enc);

    // mma.sync encode GEMM (grid x = M-tiles so each wave shares B via L2)
    cudaFuncSetAttribute(encode_gemm_mma,
                         cudaFuncAttributeMaxDynamicSharedMemorySize, SMEM_REQ);
    encode_gemm_mma<<<dim3(N_TOK / 128, D_SAE / 128), 256, SMEM_REQ>>>(b_enc, pre);

    topk_kernel<<<N_TOK, 256>>>(pre, z);

    decode_kernel<<<N_TOK, 256>>>(W_dec, b_dec, xhat);
}

// round 16
// speedup vs baseline: 2.7147x; 1.7227x over previous
#include <cuda_runtime.h>
#include <cuda_fp16.h>
#include <cuda_bf16.h>
#include <cstdint>

// Problem constants (fixed shapes for TopKSAE_128849019036)
#define N_TOK   4096
#define D_MODEL 2048
#define D_SAE   32768
#define KTOP    64

// ---------------------------------------------------------------------------
// Device-global scratch (sanctioned; no dynamic allocation).
// Scaled fp16x2 split operands:
//   g_XA0 = fl16(x),  g_XA1 = fl16((x - fl16(x)) * 2^11)
//   g_WB0 = fl16(w),  g_WB1 = fl16((w - fl16(w)) * 2^11)      (w transposed)
// The 2^11 scaling keeps the W residual (~4e-6, below fp16 min normal 6.1e-5)
// in fp16 NORMAL range — R14/R15's failure was a deterministic ~7.7e-7 'pre'
// perturbation from subnormal quantization of that residual.
// ---------------------------------------------------------------------------
__device__ __half g_XA0[(size_t)N_TOK * D_MODEL];
__device__ __half g_XA1[(size_t)N_TOK * D_MODEL];
__device__ __half g_WB0[(size_t)D_SAE * D_MODEL];
__device__ __half g_WB1[(size_t)D_SAE * D_MODEL];
__device__ float g_vals[N_TOK * KTOP];
__device__ int   g_idx [N_TOK * KTOP];

#define RSCALE     2048.0f           // 2^11
#define RSCALE_INV 4.8828125e-4f     // exact 2^-11

__device__ __forceinline__ uint32_t smem_u32(const void* p) {
    uint32_t a;
    asm("{ .reg .u64 t; cvta.to.shared.u64 t, %1; cvt.u32.u64 %0, t; }"
        : "=r"(a) : "l"(p));
    return a;
}

// scaled 2-way fp16 split: v = h0 + h1*2^-11 + O(~2e-8), h1 normal-range
__device__ __forceinline__ void split2s(float v, unsigned short& h0,
                                        unsigned short& h1) {
    __half a = __float2half_rn(v);
    float r = __fmul_rn(__fsub_rn(v, __half2float(a)), RSCALE);
    __half b = __float2half_rn(r);
    h0 = *reinterpret_cast<unsigned short*>(&a);
    h1 = *reinterpret_cast<unsigned short*>(&b);
}

// ===========================================================================
// Pre-pass 1: split x -> g_XA0/1 (same [M,K] layout)
// ===========================================================================
__global__ __launch_bounds__(256)
void split_x_kernel(const float* __restrict__ x)
{
    size_t gid = (size_t)blockIdx.x * 256 + threadIdx.x;  // over float4s
    float4 v = ((const float4*)x)[gid];
    ushort4 o0, o1;
    split2s(v.x, o0.x, o1.x);
    split2s(v.y, o0.y, o1.y);
    split2s(v.z, o0.z, o1.z);
    split2s(v.w, o0.w, o1.w);
    ((ushort4*)g_XA0)[gid] = o0;
    ((ushort4*)g_XA1)[gid] = o1;
}

// ===========================================================================
// Pre-pass 2: transpose + scaled-split W_enc [K, N] -> g_WB0/1 [N, K]
// ===========================================================================
__global__ __launch_bounds__(256)
void split_w_kernel(const float* __restrict__ W, int ybase)
{
    __shared__ float tile[32][33];
    const int kt = blockIdx.x * 32, nt = (blockIdx.y + ybase) * 32;
    const int tid = threadIdx.x;
    const int tr = tid >> 5, tc = tid & 31;
#pragma unroll
    for (int i = 0; i < 4; i++) {
        int kk = tr + i * 8;
        tile[kk][tc] = W[(size_t)(kt + kk) * D_SAE + nt + tc];
    }
    __syncthreads();
    const int nr = tid >> 3;          // 0..31
    const int kc = (tid & 7) * 4;     // 0..28
    ushort4 o0, o1;
    split2s(tile[kc + 0][nr], o0.x, o1.x);
    split2s(tile[kc + 1][nr], o0.y, o1.y);
    split2s(tile[kc + 2][nr], o0.z, o1.z);
    split2s(tile[kc + 3][nr], o0.w, o1.w);
    size_t off = ((size_t)(nt + nr) * D_MODEL + kt + kc) >> 2;  // in ushort4
    ((ushort4*)g_WB0)[off] = o0;
    ((ushort4*)g_WB1)[off] = o1;
}

// ===========================================================================
// Encode GEMM via mma.sync fp16 (legacy HMMA; tcgen05 blocked by the
// harness's compute_103 virtual arch).
//
// pre = x @ W_enc + b_enc with scaled fp16x2 splits, 3 products:
//   MAIN accumulator: x0*w0                  (chunk-folded every K=128)
//   CORR accumulator: x1s*w0 + x0*w1s        (scaled 2^11; one scale-down
//                                             multiply at the epilogue, so
//                                             its fp32 rounding is ~2e-10)
// Total pre error ~1.4e-7 rms — below the passing R9 level; the R14/15
// deterministic subnormal-residual bias is eliminated.
//
// CTA tile 128x128, BK=32, 256 threads (8 warps, warp tile m32 x n64).
// Double-buffered smem via cp.async; padded row stride 40 halves keeps
// ldmatrix conflict-free.
// ===========================================================================
#define BK      32
#define TS      40                    // padded tile row stride, in halves
#define TILE_B  (128 * TS * 2)        // 10240 B per operand tile
#define STAGE_B (4 * TILE_B)          // 40960 B per stage (A0,A1,B0,B1)
#define SMEM_REQ (2 * STAGE_B)        // 81920 B
#define NSLAB   (D_MODEL / BK)        // 64

__device__ __forceinline__ void mma16816(float* d, const uint32_t* a,
                                         const uint32_t* b) {
    asm volatile(
        "mma.sync.aligned.m16n8k16.row.col.f32.f16.f16.f32 "
        "{%0,%1,%2,%3}, {%4,%5,%6,%7}, {%8,%9}, {%0,%1,%2,%3};"
        : "+f"(d[0]), "+f"(d[1]), "+f"(d[2]), "+f"(d[3])
        : "r"(a[0]), "r"(a[1]), "r"(a[2]), "r"(a[3]), "r"(b[0]), "r"(b[1]));
}

__global__ __launch_bounds__(256, 1)
void encode_gemm_mma(const float* __restrict__ bias, float* __restrict__ C)
{
    extern __shared__ char smem[];
    const uint32_t sbase = smem_u32(smem);
    const int tid  = threadIdx.x, wid = tid >> 5, lane = tid & 31;
    const int mtile = blockIdx.x, ntile = blockIdx.y;

    const __half* src[4] = {
        g_XA0 + (size_t)mtile * 128 * D_MODEL,
        g_XA1 + (size_t)mtile * 128 * D_MODEL,
        g_WB0 + (size_t)ntile * 128 * D_MODEL,
        g_WB1 + (size_t)ntile * 128 * D_MODEL };

    auto issue_slab = [&](int t) {
        const uint32_t dstbase = sbase + (uint32_t)(t & 1) * STAGE_B;
        const size_t ks = (size_t)t * BK;
#pragma unroll
        for (int u = 0; u < 8; u++) {
            const int tile = u >> 1;
            const int op  = ((u & 1) << 8) + tid;    // 0..511
            const int r   = op >> 2, seg = op & 3;
            const __half* s = src[tile] + (size_t)r * D_MODEL + ks + seg * 8;
            const uint32_t d = dstbase + tile * TILE_B + r * (TS * 2) + seg * 16;
            asm volatile("cp.async.cg.shared.global [%0], [%1], 16;"
                         :: "r"(d), "l"(s) : "memory");
        }
        asm volatile("cp.async.commit_group;" ::: "memory");
    };

    float acc[2][8][4], sum[2][8][4], corr[2][8][4];
#pragma unroll
    for (int mi = 0; mi < 2; mi++)
#pragma unroll
        for (int nt = 0; nt < 8; nt++)
#pragma unroll
            for (int q = 0; q < 4; q++) {
                acc[mi][nt][q] = 0.f; sum[mi][nt][q] = 0.f;
                corr[mi][nt][q] = 0.f;
            }

    const int wm = (wid & 3) * 32;
    const int wn = (wid >> 2) * 64;
    const int lrow = lane & 15, lcol = lane >> 4;

    issue_slab(0);

    for (int t = 0; t < NSLAB; t++) {
        if (t + 1 < NSLAB) {
            issue_slab(t + 1);
            asm volatile("cp.async.wait_group 1;" ::: "memory");
        } else {
            asm volatile("cp.async.wait_group 0;" ::: "memory");
        }
        __syncthreads();

        const uint32_t sb = sbase + (uint32_t)(t & 1) * STAGE_B;
#pragma unroll
        for (int kstep = 0; kstep < 2; kstep++) {
            // A fragments for both splits (m32 x k16 each)
            uint32_t a[2][2][4];
#pragma unroll
            for (int ap = 0; ap < 2; ap++)
#pragma unroll
                for (int mi = 0; mi < 2; mi++) {
                    const uint32_t addr = sb + ap * TILE_B +
                        (wm + mi * 16 + lrow) * (TS * 2) + kstep * 32 + lcol * 16;
                    asm volatile(
                        "ldmatrix.sync.aligned.m8n8.x4.shared.b16 {%0,%1,%2,%3}, [%4];"
                        : "=r"(a[ap][mi][0]), "=r"(a[ap][mi][1]),
                          "=r"(a[ap][mi][2]), "=r"(a[ap][mi][3])
                        : "r"(addr));
                }
            // products: (a0,b0)->MAIN; (a1,b0),(a0,b1)->CORR (scaled 2^11)
#pragma unroll
            for (int bp = 0; bp < 2; bp++) {
                uint32_t bf[8][2];
#pragma unroll
                for (int nb = 0; nb < 4; nb++) {
                    uint32_t r0, r1, r2, r3;
                    const uint32_t addr = sb + (2 + bp) * TILE_B +
                        (wn + nb * 16 + lrow) * (TS * 2) + kstep * 32 + lcol * 16;
                    asm volatile(
                        "ldmatrix.sync.aligned.m8n8.x4.shared.b16 {%0,%1,%2,%3}, [%4];"
                        : "=r"(r0), "=r"(r1), "=r"(r2), "=r"(r3)
                        : "r"(addr));
                    bf[2 * nb][0] = r0;  bf[2 * nb][1] = r2;
                    bf[2 * nb + 1][0] = r1;  bf[2 * nb + 1][1] = r3;
                }
#pragma unroll
                for (int ap = 0; ap < 2; ap++) {
                    if (ap + bp <= 1) {   // 3 products: i+j<=1
                        const bool main = (ap == 0) && (bp == 0);
#pragma unroll
                        for (int mi = 0; mi < 2; mi++)
#pragma unroll
                            for (int nt = 0; nt < 8; nt++)
                                mma16816(main ? acc[mi][nt] : corr[mi][nt],
                                         a[ap][mi], bf[nt]);
                    }
                }
            }
        }
        __syncthreads();

        if ((t & 3) == 3) {   // MAIN chunk fold every K=128
#pragma unroll
            for (int mi = 0; mi < 2; mi++)
#pragma unroll
                for (int nt = 0; nt < 8; nt++)
#pragma unroll
                    for (int q = 0; q < 4; q++) {
                        sum[mi][nt][q] = __fadd_rn(sum[mi][nt][q], acc[mi][nt][q]);
                        acc[mi][nt][q] = 0.f;
                    }
        }
    }

    // epilogue: pre = (sum + corr*2^-11) + bias   (deterministic order)
#pragma unroll
    for (int mi = 0; mi < 2; mi++)
#pragma unroll
        for (int nt = 0; nt < 8; nt++) {
            const int row = mtile * 128 + wm + mi * 16 + (lane >> 2);
            const int col = ntile * 128 + wn + nt * 8 + (lane & 3) * 2;
            const float b0 = bias[col], b1 = bias[col + 1];
            float2 v0, v1;
            v0.x = __fadd_rn(__fadd_rn(sum[mi][nt][0],
                     __fmul_rn(corr[mi][nt][0], RSCALE_INV)), b0);
            v0.y = __fadd_rn(__fadd_rn(sum[mi][nt][1],
                     __fmul_rn(corr[mi][nt][1], RSCALE_INV)), b1);
            v1.x = __fadd_rn(__fadd_rn(sum[mi][nt][2],
                     __fmul_rn(corr[mi][nt][2], RSCALE_INV)), b0);
            v1.y = __fadd_rn(__fadd_rn(sum[mi][nt][3],
                     __fmul_rn(corr[mi][nt][3], RSCALE_INV)), b1);
            *(float2*)(C + (size_t)row * D_SAE + col)       = v0;
            *(float2*)(C + (size_t)(row + 8) * D_SAE + col) = v1;
        }
}

// ============================================================================
// Top-64 of relu(pre) — exact selection (values desc, ties lowest-index,
// matches jax.lax.top_k). 11-bit histogram + suffix scan + candidate
// collection + O(c^2) rank selection. (Unchanged from passing R13.)
// ============================================================================
#define NBIN 2048
#define CAND 2048

__global__ __launch_bounds__(256)
void topk_kernel(const float* __restrict__ pre, float* __restrict__ z)
{
    __shared__ int   hist[2][NBIN];
    __shared__ int   s_scan[256];
    __shared__ float cv[CAND];
    __shared__ int   ci[CAND];
    __shared__ int   s_cnt, s_B, s_K;

    const int tid = threadIdx.x;           // 256 threads
    const int n   = blockIdx.x;
    const float* row = pre + (size_t)n * D_SAE;
    const int h = (tid >> 5) & 1;

    for (int i = tid; i < NBIN; i += 256) { hist[0][i] = 0; hist[1][i] = 0; }
    if (tid < KTOP) { g_vals[n * KTOP + tid] = 0.f; g_idx[n * KTOP + tid] = 0; }
    if (tid == 0) s_cnt = 0;
    __syncthreads();

    for (int i = tid; i < D_SAE / 4; i += 256) {
        float4 v = ((const float4*)row)[i];
        if (v.x > 0.f) atomicAdd(&hist[h][__float_as_uint(v.x) >> 20], 1);
        if (v.y > 0.f) atomicAdd(&hist[h][__float_as_uint(v.y) >> 20], 1);
        if (v.z > 0.f) atomicAdd(&hist[h][__float_as_uint(v.z) >> 20], 1);
        if (v.w > 0.f) atomicAdd(&hist[h][__float_as_uint(v.w) >> 20], 1);
    }
    __syncthreads();

    int tsum = 0;
#pragma unroll
    for (int b = 0; b < 8; b++) {
        const int bb = tid * 8 + b;
        const int c = hist[0][bb] + hist[1][bb];
        hist[0][bb] = c;
        tsum += c;
    }
    s_scan[tid] = tsum;
    __syncthreads();

    for (int off = 1; off < 256; off <<= 1) {
        int v = (tid + off < 256) ? s_scan[tid + off] : 0;
        __syncthreads();
        s_scan[tid] += v;
        __syncthreads();
    }
    const int total = s_scan[0];

    if (total <= KTOP) {
        if (tid == 0) { s_B = 0; s_K = total; }
    } else {
        const int above = (tid < 255) ? s_scan[tid + 1] : 0;
        if (s_scan[tid] >= KTOP && above < KTOP) {
            int cum = above, B = tid * 8;
#pragma unroll
            for (int b = 7; b >= 0; b--) {
                cum += hist[0][tid * 8 + b];
                if (cum >= KTOP) { B = tid * 8 + b; break; }
            }
            s_B = B; s_K = KTOP;
        }
    }
    __syncthreads();
    const unsigned B = (unsigned)s_B;
    const int Ksel = s_K;

    for (int i = tid; i < D_SAE / 4; i += 256) {
        float4 v = ((const float4*)row)[i];
        const int base = 4 * i;
        if (v.x > 0.f && (__float_as_uint(v.x) >> 20) >= B) {
            int p = atomicAdd(&s_cnt, 1);
            if (p < CAND) { cv[p] = v.x; ci[p] = base; }
        }
        if (v.y > 0.f && (__float_as_uint(v.y) >> 20) >= B) {
            int p = atomicAdd(&s_cnt, 1);
            if (p < CAND) { cv[p] = v.y; ci[p] = base + 1; }
        }
        if (v.z > 0.f && (__float_as_uint(v.z) >> 20) >= B) {
            int p = atomicAdd(&s_cnt, 1);
            if (p < CAND) { cv[p] = v.z; ci[p] = base + 2; }
        }
        if (v.w > 0.f && (__float_as_uint(v.w) >> 20) >= B) {
            int p = atomicAdd(&s_cnt, 1);
            if (p < CAND) { cv[p] = v.w; ci[p] = base + 3; }
        }
    }
    __syncthreads();
    const int c = min(s_cnt, CAND);

    for (int p = tid; p < c; p += 256) {
        const float vp = cv[p];
        const int   ip = ci[p];
        int rank = 0;
        for (int q = 0; q < c; q++) {
            const float vq = cv[q];
            rank += (vq > vp) || (vq == vp && ci[q] < ip);
        }
        if (rank < Ksel) {
            g_vals[n * KTOP + rank] = vp;
            g_idx [n * KTOP + rank] = ip;
            z[(size_t)n * D_SAE + ip] = vp;
        }
    }
}

// ============================================================================
// Sparse decode  x_hat[n] = sum_k v_k * W_dec[idx_k, :] + b_dec
// ============================================================================
__global__ __launch_bounds__(256)
void decode_kernel(const float* __restrict__ Wdec,
                   const float* __restrict__ bdec,
                   float* __restrict__ xhat)
{
    __shared__ float sv[KTOP];
    __shared__ int   si[KTOP];
    const int n = blockIdx.x, tid = threadIdx.x;
    if (tid < KTOP) {
        sv[tid] = g_vals[n * KTOP + tid];
        si[tid] = g_idx [n * KTOP + tid];
    }
    __syncthreads();

    float acc[8];
#pragma unroll
    for (int j = 0; j < 8; j++) acc[j] = bdec[tid + j * 256];

    for (int k = 0; k < KTOP; k++) {
        float v = sv[k];
        const float* wr = Wdec + (size_t)si[k] * D_MODEL;
#pragma unroll
        for (int j = 0; j < 8; j++)
            acc[j] = fmaf(v, wr[tid + j * 256], acc[j]);
    }

    float* orow = xhat + (size_t)n * D_MODEL;
#pragma unroll
    for (int j = 0; j < 8; j++) orow[tid + j * 256] = acc[j];
}

// ============================================================================
// Launch: out = [x_hat | z | pre], all fp32. Graph-capturable.
// ============================================================================
extern "C" void kernel_launch(void* const* d_in, const int* in_sizes, int n_in,
                              void* d_out, int out_size)
{
    (void)in_sizes; (void)n_in; (void)out_size;
    const float* x     = (const float*)d_in[0];
    const float* W_enc = (const float*)d_in[1];
    const float* b_enc = (const float*)d_in[2];
    const float* W_dec = (const float*)d_in[3];
    const float* b_dec = (const float*)d_in[4];

    float* out  = (float*)d_out;
    float* xhat = out;
    float* z    = out + (size_t)N_TOK * D_MODEL;
    float* pre  = z   + (size_t)N_TOK * D_SAE;

    cudaMemsetAsync(z, 0, (size_t)N_TOK * D_SAE * sizeof(float), 0);

    // pre-pass: scaled fp16x2 splits
    split_x_kernel<<<(N_TOK * D_MODEL / 4) / 256, 256>>>(x);
    split_w_kernel<<<dim3(D_MODEL / 32, D_SAE / 64), 256>>>(W_enc, 0);
    split_w_kernel<<<dim3(D_MODEL / 32, D_SAE / 64), 256>>>(W_enc, D_SAE / 64);

    // fp16x2 mma.sync encode GEMM (grid x = M-tiles: each wave shares B via L2)
    cudaFuncSetAttribute(encode_gemm_mma,
                         cudaFuncAttributeMaxDynamicSharedMemorySize, SMEM_REQ);
    encode_gemm_mma<<<dim3(N_TOK / 128, D_SAE / 128), 256, SMEM_REQ>>>(b_enc, pre);

    topk_kernel<<<N_TOK, 256>>>(pre, z);

    decode_kernel<<<N_TOK, 256>>>(W_dec, b_dec, xhat);
}